// round 15
// baseline (speedup 1.0000x reference)
#include <cuda_runtime.h>
#include <cuda_bf16.h>
#include <math.h>
#include <stdint.h>

#define B_   512
#define NW   64
#define NQ   343
#define NTOK 344
#define DIM  96
#define H    3
#define HD   32
#define NROWS (B_*NTOK)
#define XOUT_SZ ((size_t)B_*NQ*DIM)
#define BMSTR 344
#define RLN2  1.4426950408889634f

typedef unsigned long long u64;

__device__ float g_att[(size_t)B_*NTOK*DIM];
__device__ float g_bm[(size_t)H*NW*NQ*BMSTR + 16];

// ---------------- kernel 0: bm gather, x4, pre-scaled by log2(e) ----------
__global__ void bm_pre_kernel(const float* __restrict__ btab,
                              const int* __restrict__ ri,
                              const float* __restrict__ mask) {
    size_t gid = (size_t)blockIdx.x * 256 + threadIdx.x;
    if (gid >= (size_t)H*NW*NQ*86) return;
    int q  = (int)(gid % 86);
    size_t t = gid / 86;
    int r  = (int)(t % NQ);
    int hw = (int)(t / NQ);
    int h = hw / NW, w = hw % NW;
    int j0 = q*4;
    const int*   rr = ri + (size_t)r*NQ;
    const float* mr = mask + (size_t)w*NQ*NQ + (size_t)r*NQ;
    float v[4];
    #pragma unroll
    for (int e = 0; e < 4; ++e) {
        int j = j0 + e;
        v[e] = 0.f;
        if (j >= 1)
            v[e] = (btab[rr[j-1]*H + h] + mr[j-1]) * RLN2;
    }
    *(float4*)&g_bm[((size_t)hw*NQ + r)*BMSTR + j0] =
        make_float4(v[0], v[1], v[2], v[3]);
}

// ---------------- helpers ----------------
__device__ __forceinline__ uint32_t pack_bf16(float lo, float hi) {
    uint32_t r;
    asm("cvt.rn.bf16x2.f32 %0, %1, %2;" : "=r"(r) : "f"(hi), "f"(lo));
    return r;
}
__device__ __forceinline__ u64 pk2(float lo, float hi) {
    u64 r; asm("mov.b64 %0, {%1, %2};" : "=l"(r) : "f"(lo), "f"(hi)); return r;
}
__device__ __forceinline__ void upk2(float& lo, float& hi, u64 v) {
    asm("mov.b64 {%0, %1}, %2;" : "=f"(lo), "=f"(hi) : "l"(v));
}
__device__ __forceinline__ void fma2(u64& d, u64 a, u64 b) {
    asm("fma.rn.f32x2 %0, %1, %2, %3;" : "=l"(d) : "l"(a), "l"(b), "l"(d));
}
__device__ __forceinline__ float ex2f(float x) {
    float r; asm("ex2.approx.f32 %0, %1;" : "=f"(r) : "f"(x)); return r;
}

#define MMA_BF16(d, a0,a1,a2,a3, b0,b1)                                      \
    asm volatile("mma.sync.aligned.m16n8k16.row.col.f32.bf16.bf16.f32 "      \
        "{%0,%1,%2,%3},{%4,%5,%6,%7},{%8,%9},{%0,%1,%2,%3};"                 \
        : "+f"(d[0]), "+f"(d[1]), "+f"(d[2]), "+f"(d[3])                      \
        : "r"(a0), "r"(a1), "r"(a2), "r"(a3), "r"(b0), "r"(b1))

// fused smem layout (bytes):
//  phase1 aliases: Xp u32[352][26] @0 (36608) | Wp u32[48][104] @36608 | bis @56576
//  phase2: P u64/warp [16][18] @wid*2304, region [0,50688)
//          Qs @56960 (47872) | Kt @104832 (45568) | Vt @150400 (45568, [32][356])
#define SM_XP   0
#define SM_WP   36608
#define SM_BS   56576
#define SM_QS   56960
#define SM_KT   104832
#define SM_VT   150400
#define FUSED_SMEM 201088

__global__ void __launch_bounds__(704, 1)
fused_attn_kernel(const float* __restrict__ x,
                  const float* __restrict__ gt,
                  const float* __restrict__ Wqkv,
                  const float* __restrict__ bqkv) {
    extern __shared__ char smem[];
    uint32_t* Xp = (uint32_t*)(smem + SM_XP);
    uint32_t* Wp = (uint32_t*)(smem + SM_WP);
    float* bis = (float*)(smem + SM_BS);
    float* Qs  = (float*)(smem + SM_QS);
    float* Kt  = (float*)(smem + SM_KT);
    float* Vt  = (float*)(smem + SM_VT);   // [32][356] transposed

    const int bid = blockIdx.x;
    const int rep = bid & 7;
    const int hw  = bid >> 3;
    const int w   = hw & 63;
    const int h   = hw >> 6;
    const int b   = (rep << 6) + w;

    const int tid  = threadIdx.x;
    const int wid  = tid >> 5;
    const int lane = tid & 31;
    const int g    = lane >> 2;
    const int tg   = lane & 3;
    const float scale = 0.17677669529663687f * RLN2;
    const int mb = wid * 16;

    // ---- W and bias fill ----
    for (int idx = tid; idx < 48*96; idx += 704) {
        int k2 = idx / 96, c = idx % 96;
        int row = (c < 32) ? (h*HD + c)
                : (c < 64) ? (DIM + h*HD + (c-32))
                           : (2*DIM + h*HD + (c-64));
        const float* wr = Wqkv + (size_t)row*DIM + 2*k2;
        Wp[k2*104 + c] = pack_bf16(wr[0], wr[1]);
    }
    if (tid < 96) {
        int c = tid;
        int row = (c < 32) ? (h*HD + c)
                : (c < 64) ? (DIM + h*HD + (c-32))
                           : (2*DIM + h*HD + (c-64));
        bis[c] = bqkv[row];
    }

    // ---- phase 1: two-pass bf16 MMA GEMM (R13 proven) ----
    float c4[12][4];
    #pragma unroll
    for (int nt = 0; nt < 12; ++nt)
        #pragma unroll
        for (int e = 0; e < 4; ++e) c4[nt][e] = 0.f;

    for (int pass = 0; pass < 2; ++pass) {
        if (pass) __syncthreads();
        for (int idx = tid; idx < 352*24; idx += 704) {
            int n = idx / 24, p = idx % 24;
            float a = 0.f, cc = 0.f;
            if (n < NTOK) {
                const float* src = (n == 0) ? (gt + (size_t)b*DIM)
                                            : (x + ((size_t)b*NQ + (n-1))*DIM);
                float2 v2 = *(const float2*)(src + pass*48 + 2*p);
                a = v2.x; cc = v2.y;
            }
            Xp[n*26 + p] = pack_bf16(a, cc);
        }
        __syncthreads();
        uint32_t xa[3][4];
        #pragma unroll
        for (int kt = 0; kt < 3; ++kt) {
            xa[kt][0] = Xp[(mb+g)*26   + kt*8 + tg];
            xa[kt][1] = Xp[(mb+g+8)*26 + kt*8 + tg];
            xa[kt][2] = Xp[(mb+g)*26   + kt*8 + tg + 4];
            xa[kt][3] = Xp[(mb+g+8)*26 + kt*8 + tg + 4];
        }
        #pragma unroll
        for (int nt = 0; nt < 12; ++nt)
            #pragma unroll
            for (int kt = 0; kt < 3; ++kt) {
                int kr = (pass*3 + kt)*8 + tg;
                uint32_t b0 = Wp[kr*104 + nt*8 + g];
                uint32_t b1 = Wp[(kr+4)*104 + nt*8 + g];
                MMA_BF16(c4[nt], xa[kt][0], xa[kt][1], xa[kt][2], xa[kt][3], b0, b1);
            }
    }
    // epilogue: Qs (pair-interleaved, scaled) / Kt / Vt (both transposed)
    #pragma unroll
    for (int nt = 0; nt < 12; ++nt) {
        float bia = bis[nt*8 + 2*tg];
        float bib = bis[nt*8 + 2*tg + 1];
        float v0 = c4[nt][0] + bia, v1 = c4[nt][1] + bib;
        float v2 = c4[nt][2] + bia, v3 = c4[nt][3] + bib;
        const int sec = nt >> 2, ntr = nt & 3;
        const int d0 = ntr*8 + 2*tg;
        const int n1 = mb + g, n2 = n1 + 8;
        if (sec == 0) {
            Qs[(n1>>1)*68 + d0*2     + (n1&1)] = v0*scale;
            Qs[(n1>>1)*68 + (d0+1)*2 + (n1&1)] = v1*scale;
            Qs[(n2>>1)*68 + d0*2     + (n2&1)] = v2*scale;
            Qs[(n2>>1)*68 + (d0+1)*2 + (n2&1)] = v3*scale;
        } else if (sec == 1) {
            Kt[d0*356 + n1] = v0; Kt[(d0+1)*356 + n1] = v1;
            Kt[d0*356 + n2] = v2; Kt[(d0+1)*356 + n2] = v3;
        } else {
            Vt[d0*356 + n1] = v0; Vt[(d0+1)*356 + n1] = v1;
            Vt[d0*356 + n2] = v2; Vt[(d0+1)*356 + n2] = v3;
        }
    }
    __syncthreads();

    // ---- phase 2: f32x2 attention, j-paired PV ----
    const int tq = lane >> 3;
    const int tk = lane & 7;
    u64* Pw = (u64*)(smem + wid*2304);   // [16 q][18] u64 per warp
    const float* bmb = g_bm + ((size_t)(h*NW + w)) * NQ * BMSTR;
    const int q0 = mb + tq*4;
    const int ql = tq*4;

    u64 o2[4][4];          // [qi][di], (even-j sum, odd-j sum)
    float l4[4] = {0.f, 0.f, 0.f, 0.f};
    #pragma unroll
    for (int qi = 0; qi < 4; ++qi)
        #pragma unroll
        for (int di = 0; di < 4; ++di) o2[qi][di] = pk2(0.f, 0.f);

    for (int kb = 0; kb < 11; ++kb) {
        const int kbase = kb*32;

        // ---- S = Q K^T (q-paired accumulators, 2-d steps) ----
        u64 acc2[2][4];
        #pragma unroll
        for (int p = 0; p < 2; ++p)
            #pragma unroll
            for (int c = 0; c < 4; ++c) acc2[p][c] = pk2(0.f, 0.f);

        const float* kp = Kt + kbase + tk*4;
        const float* qp = Qs + (q0>>1)*68;
        #pragma unroll
        for (int d = 0; d < 32; d += 2) {
            ulonglong2 qa2 = *(const ulonglong2*)(qp + 2*d);       // q-pair row0: d, d+1
            ulonglong2 qb2 = *(const ulonglong2*)(qp + 68 + 2*d);  // q-pair row1
            float4 kv0 = *(const float4*)(kp + d*356);
            float4 kv1 = *(const float4*)(kp + (d+1)*356);
            u64 ka0 = pk2(kv0.x, kv0.x), ka1 = pk2(kv0.y, kv0.y);
            u64 ka2 = pk2(kv0.z, kv0.z), ka3 = pk2(kv0.w, kv0.w);
            u64 kb0 = pk2(kv1.x, kv1.x), kb1 = pk2(kv1.y, kv1.y);
            u64 kb2 = pk2(kv1.z, kv1.z), kb3 = pk2(kv1.w, kv1.w);
            fma2(acc2[0][0], qa2.x, ka0); fma2(acc2[0][1], qa2.x, ka1);
            fma2(acc2[0][2], qa2.x, ka2); fma2(acc2[0][3], qa2.x, ka3);
            fma2(acc2[0][0], qa2.y, kb0); fma2(acc2[0][1], qa2.y, kb1);
            fma2(acc2[0][2], qa2.y, kb2); fma2(acc2[0][3], qa2.y, kb3);
            fma2(acc2[1][0], qb2.x, ka0); fma2(acc2[1][1], qb2.x, ka1);
            fma2(acc2[1][2], qb2.x, ka2); fma2(acc2[1][3], qb2.x, ka3);
            fma2(acc2[1][0], qb2.y, kb0); fma2(acc2[1][1], qb2.y, kb1);
            fma2(acc2[1][2], qb2.y, kb2); fma2(acc2[1][3], qb2.y, kb3);
        }

        // ---- exp2 + bm; write P j-paired ----
        #pragma unroll
        for (int p = 0; p < 2; ++p) {
            int re = q0 + 2*p, ro = re + 1;
            bool vqe = (re >= 1) && (re < NTOK);
            bool vqo = (ro < NTOK);
            float4 bme = vqe ? __ldg((const float4*)(bmb + (size_t)(re-1)*BMSTR + kbase + tk*4))
                             : make_float4(0.f,0.f,0.f,0.f);
            float4 bmo = vqo ? __ldg((const float4*)(bmb + (size_t)(ro-1)*BMSTR + kbase + tk*4))
                             : make_float4(0.f,0.f,0.f,0.f);
            float be[4] = {bme.x, bme.y, bme.z, bme.w};
            float bo[4] = {bmo.x, bmo.y, bmo.z, bmo.w};
            float pe[4], po[4];
            #pragma unroll
            for (int c = 0; c < 4; ++c) {
                float se, so;
                upk2(se, so, acc2[p][c]);
                int j = kbase + tk*4 + c;
                pe[c] = (j < NTOK) ? ex2f(se + be[c]) : 0.f;
                po[c] = (j < NTOK) ? ex2f(so + bo[c]) : 0.f;
                l4[2*p]   += pe[c];
                l4[2*p+1] += po[c];
            }
            Pw[(ql + 2*p)*18 + tk*2]     = pk2(pe[0], pe[1]);
            Pw[(ql + 2*p)*18 + tk*2 + 1] = pk2(pe[2], pe[3]);
            Pw[(ql + 2*p + 1)*18 + tk*2]     = pk2(po[0], po[1]);
            Pw[(ql + 2*p + 1)*18 + tk*2 + 1] = pk2(po[2], po[3]);
        }
        __syncwarp();

        // ---- O += P V  (all loads natural pairs; no movs) ----
        const float* vb = Vt + kbase + tk*0;   // base; row offset added below
        #pragma unroll
        for (int s = 0; s < 8; ++s) {
            const int col = kbase + s*4;
            ulonglong2 pq0 = *(const ulonglong2*)&Pw[(ql+0)*18 + s*2];
            ulonglong2 pq1 = *(const ulonglong2*)&Pw[(ql+1)*18 + s*2];
            ulonglong2 pq2 = *(const ulonglong2*)&Pw[(ql+2)*18 + s*2];
            ulonglong2 pq3 = *(const ulonglong2*)&Pw[(ql+3)*18 + s*2];
            ulonglong2 vv0 = *(const ulonglong2*)(Vt + (tk*4+0)*356 + col);
            ulonglong2 vv1 = *(const ulonglong2*)(Vt + (tk*4+1)*356 + col);
            ulonglong2 vv2 = *(const ulonglong2*)(Vt + (tk*4+2)*356 + col);
            ulonglong2 vv3 = *(const ulonglong2*)(Vt + (tk*4+3)*356 + col);
            fma2(o2[0][0], pq0.x, vv0.x); fma2(o2[0][0], pq0.y, vv0.y);
            fma2(o2[0][1], pq0.x, vv1.x); fma2(o2[0][1], pq0.y, vv1.y);
            fma2(o2[0][2], pq0.x, vv2.x); fma2(o2[0][2], pq0.y, vv2.y);
            fma2(o2[0][3], pq0.x, vv3.x); fma2(o2[0][3], pq0.y, vv3.y);
            fma2(o2[1][0], pq1.x, vv0.x); fma2(o2[1][0], pq1.y, vv0.y);
            fma2(o2[1][1], pq1.x, vv1.x); fma2(o2[1][1], pq1.y, vv1.y);
            fma2(o2[1][2], pq1.x, vv2.x); fma2(o2[1][2], pq1.y, vv2.y);
            fma2(o2[1][3], pq1.x, vv3.x); fma2(o2[1][3], pq1.y, vv3.y);
            fma2(o2[2][0], pq2.x, vv0.x); fma2(o2[2][0], pq2.y, vv0.y);
            fma2(o2[2][1], pq2.x, vv1.x); fma2(o2[2][1], pq2.y, vv1.y);
            fma2(o2[2][2], pq2.x, vv2.x); fma2(o2[2][2], pq2.y, vv2.y);
            fma2(o2[2][3], pq2.x, vv3.x); fma2(o2[2][3], pq2.y, vv3.y);
            fma2(o2[3][0], pq3.x, vv0.x); fma2(o2[3][0], pq3.y, vv0.y);
            fma2(o2[3][1], pq3.x, vv1.x); fma2(o2[3][1], pq3.y, vv1.y);
            fma2(o2[3][2], pq3.x, vv2.x); fma2(o2[3][2], pq3.y, vv2.y);
            fma2(o2[3][3], pq3.x, vv3.x); fma2(o2[3][3], pq3.y, vv3.y);
        }
        __syncwarp();
    }

    // ---- reduce l over tk group, fold jpairs, normalize, store ----
    #pragma unroll
    for (int a = 0; a < 4; ++a) {
        l4[a] += __shfl_xor_sync(0xffffffffu, l4[a], 1);
        l4[a] += __shfl_xor_sync(0xffffffffu, l4[a], 2);
        l4[a] += __shfl_xor_sync(0xffffffffu, l4[a], 4);
    }
    #pragma unroll
    for (int qi = 0; qi < 4; ++qi) {
        int n = q0 + qi;
        if (n < NTOK) {
            float inv = 1.f / l4[qi];
            float ov[4];
            #pragma unroll
            for (int di = 0; di < 4; ++di) {
                float lo, hi;
                upk2(lo, hi, o2[qi][di]);
                ov[di] = (lo + hi) * inv;
            }
            *(float4*)(g_att + ((size_t)b*NTOK + n)*DIM + h*HD + tk*4) =
                make_float4(ov[0], ov[1], ov[2], ov[3]);
        }
    }
}

// ---------------- proj: R12 proven f32x2 version (unchanged) ----------------
#define PROJ_SMEM (25088 + 38784)
__global__ void __launch_bounds__(256, 3)
proj_kernel(const float* __restrict__ W,
            const float* __restrict__ bp,
            float* __restrict__ dout) {
    extern __shared__ char psm[];
    float* Ai  = (float*)psm;               // [32][196]
    float* Wsm = (float*)(psm + 25088);     // [96][101]
    const int tid  = threadIdx.x;
    const int row0 = blockIdx.x * 64;
    const int rg = tid >> 5;
    const int cg = tid & 31;

    for (int idx = tid; idx < 32*24; idx += 256) {
        int rp = idx / 24, kq = idx % 24;
        float4 e = *(const float4*)(g_att + (size_t)(row0 + 2*rp)*DIM + 4*kq);
        float4 o = *(const float4*)(g_att + (size_t)(row0 + 2*rp + 1)*DIM + 4*kq);
        *(float4*)&Ai[rp*196 + 8*kq]     = make_float4(e.x, o.x, e.y, o.y);
        *(float4*)&Ai[rp*196 + 8*kq + 4] = make_float4(e.z, o.z, e.w, o.w);
    }
    for (int idx = tid; idx < 96*24; idx += 256) {
        int c = idx / 24, kq = idx % 24;
        float4 wv = *(const float4*)(W + (size_t)c*DIM + 4*kq);
        Wsm[c*101 + 4*kq]     = wv.x;
        Wsm[c*101 + 4*kq + 1] = wv.y;
        Wsm[c*101 + 4*kq + 2] = wv.z;
        Wsm[c*101 + 4*kq + 3] = wv.w;
    }
    __syncthreads();

    u64 a2[4][3];
    #pragma unroll
    for (int i = 0; i < 4; ++i)
        #pragma unroll
        for (int j = 0; j < 3; ++j) a2[i][j] = pk2(0.f, 0.f);

    const float* arow = Ai + rg*4*196;
    const float* wrow = Wsm + cg*3*101;
    #pragma unroll 4
    for (int k = 0; k < 96; ++k) {
        u64 x2[4];
        #pragma unroll
        for (int i = 0; i < 4; ++i)
            x2[i] = *(const u64*)(arow + i*196 + 2*k);
        u64 w0 = pk2(wrow[k],       wrow[k]);
        u64 w1 = pk2(wrow[101 + k], wrow[101 + k]);
        u64 w2 = pk2(wrow[202 + k], wrow[202 + k]);
        #pragma unroll
        for (int i = 0; i < 4; ++i) {
            fma2(a2[i][0], x2[i], w0);
            fma2(a2[i][1], x2[i], w1);
            fma2(a2[i][2], x2[i], w2);
        }
    }

    #pragma unroll
    for (int i = 0; i < 4; ++i) {
        #pragma unroll
        for (int j = 0; j < 3; ++j) {
            float ve, vo;
            upk2(ve, vo, a2[i][j]);
            int c = cg*3 + j;
            float bb = __ldg(bp + c);
            ve += bb; vo += bb;
            int gre = row0 + (rg*4 + i)*2;
            int gro = gre + 1;
            int be_ = gre / NTOK, ne = gre % NTOK;
            int bo_ = gro / NTOK, no = gro % NTOK;
            if (ne == 0) dout[XOUT_SZ + (size_t)be_*DIM + c] = ve;
            else         dout[((size_t)be_*NQ + (ne-1))*DIM + c] = ve;
            if (no == 0) dout[XOUT_SZ + (size_t)bo_*DIM + c] = vo;
            else         dout[((size_t)bo_*NQ + (no-1))*DIM + c] = vo;
        }
    }
}

// ---------------- launch ----------------
extern "C" void kernel_launch(void* const* d_in, const int* in_sizes, int n_in,
                              void* d_out, int out_size) {
    const float* x     = (const float*)d_in[0];
    const float* gt    = (const float*)d_in[1];
    const float* mask  = (const float*)d_in[2];
    const int*   ri    = (const int*)  d_in[3];
    const float* Wqkv  = (const float*)d_in[4];
    const float* bqkv  = (const float*)d_in[5];
    const float* Wproj = (const float*)d_in[6];
    const float* bproj = (const float*)d_in[7];
    const float* btab  = (const float*)d_in[8];
    float* out = (float*)d_out;

    cudaFuncSetAttribute(fused_attn_kernel, cudaFuncAttributeMaxDynamicSharedMemorySize, FUSED_SMEM);
    cudaFuncSetAttribute(proj_kernel,       cudaFuncAttributeMaxDynamicSharedMemorySize, PROJ_SMEM);

    {
        size_t total = (size_t)H*NW*NQ*86;
        bm_pre_kernel<<<(unsigned)((total + 255)/256), 256>>>(btab, ri, mask);
    }
    fused_attn_kernel<<<B_*H, 704, FUSED_SMEM>>>(x, gt, Wqkv, bqkv);
    proj_kernel<<<NROWS/64, 256, PROJ_SMEM>>>(Wproj, bproj, out);
}

// round 16
// speedup vs baseline: 1.5880x; 1.5880x over previous
#include <cuda_runtime.h>
#include <cuda_bf16.h>
#include <math.h>
#include <stdint.h>

#define B_   512
#define NW   64
#define NQ   343
#define NTOK 344
#define DIM  96
#define H    3
#define HD   32
#define NROWS (B_*NTOK)
#define XOUT_SZ ((size_t)B_*NQ*DIM)
#define BMSTR 344
#define RLN2  1.4426950408889634f

typedef unsigned long long u64;

__device__ float g_att[(size_t)B_*NTOK*DIM];
__device__ float g_bm[(size_t)H*NW*NQ*BMSTR + 16];

// ---------------- kernel 0: bm gather, x4, pre-scaled by log2(e) ----------
__global__ void bm_pre_kernel(const float* __restrict__ btab,
                              const int* __restrict__ ri,
                              const float* __restrict__ mask) {
    size_t gid = (size_t)blockIdx.x * 256 + threadIdx.x;
    if (gid >= (size_t)H*NW*NQ*86) return;
    int q  = (int)(gid % 86);
    size_t t = gid / 86;
    int r  = (int)(t % NQ);
    int hw = (int)(t / NQ);
    int h = hw / NW, w = hw % NW;
    int j0 = q*4;
    const int*   rr = ri + (size_t)r*NQ;
    const float* mr = mask + (size_t)w*NQ*NQ + (size_t)r*NQ;
    float v[4];
    #pragma unroll
    for (int e = 0; e < 4; ++e) {
        int j = j0 + e;
        v[e] = 0.f;
        if (j >= 1)
            v[e] = (btab[rr[j-1]*H + h] + mr[j-1]) * RLN2;
    }
    *(float4*)&g_bm[((size_t)hw*NQ + r)*BMSTR + j0] =
        make_float4(v[0], v[1], v[2], v[3]);
}

// ---------------- helpers ----------------
__device__ __forceinline__ uint32_t pack_bf16(float lo, float hi) {
    uint32_t r;
    asm("cvt.rn.bf16x2.f32 %0, %1, %2;" : "=r"(r) : "f"(hi), "f"(lo));
    return r;
}
__device__ __forceinline__ u64 pk2(float lo, float hi) {
    u64 r; asm("mov.b64 %0, {%1, %2};" : "=l"(r) : "f"(lo), "f"(hi)); return r;
}
__device__ __forceinline__ void upk2(float& lo, float& hi, u64 v) {
    asm("mov.b64 {%0, %1}, %2;" : "=f"(lo), "=f"(hi) : "l"(v));
}
__device__ __forceinline__ void fma2(u64& d, u64 a, u64 b) {
    asm("fma.rn.f32x2 %0, %1, %2, %3;" : "=l"(d) : "l"(a), "l"(b), "l"(d));
}
__device__ __forceinline__ float ex2f(float x) {
    float r; asm("ex2.approx.f32 %0, %1;" : "=f"(r) : "f"(x)); return r;
}

#define MMA_BF16(d, a0,a1,a2,a3, b0,b1)                                      \
    asm volatile("mma.sync.aligned.m16n8k16.row.col.f32.bf16.bf16.f32 "      \
        "{%0,%1,%2,%3},{%4,%5,%6,%7},{%8,%9},{%0,%1,%2,%3};"                 \
        : "+f"(d[0]), "+f"(d[1]), "+f"(d[2]), "+f"(d[3])                      \
        : "r"(a0), "r"(a1), "r"(a2), "r"(a3), "r"(b0), "r"(b1))

// fused smem layout (bytes) — identical to R13
#define SM_XP   0
#define SM_WP   36608
#define SM_BS   56576
#define SM_QS   56960
#define SM_KT   104832
#define SM_VS   150400
#define FUSED_SMEM 201088

__global__ void __launch_bounds__(704, 1)
fused_attn_kernel(const float* __restrict__ x,
                  const float* __restrict__ gt,
                  const float* __restrict__ Wqkv,
                  const float* __restrict__ bqkv) {
    extern __shared__ char smem[];
    uint32_t* Xp = (uint32_t*)(smem + SM_XP);
    uint32_t* Wp = (uint32_t*)(smem + SM_WP);
    float* bis = (float*)(smem + SM_BS);
    float* Qs  = (float*)(smem + SM_QS);
    float* Kt  = (float*)(smem + SM_KT);
    float* Vs  = (float*)(smem + SM_VS);

    const int bid = blockIdx.x;
    const int rep = bid & 7;
    const int hw  = bid >> 3;
    const int w   = hw & 63;
    const int h   = hw >> 6;
    const int b   = (rep << 6) + w;

    const int tid  = threadIdx.x;
    const int wid  = tid >> 5;
    const int lane = tid & 31;
    const int g    = lane >> 2;
    const int tg   = lane & 3;
    const float scale = 0.17677669529663687f * RLN2;
    const int mb = wid * 16;

    // ---- W and bias fill (once) ----
    for (int idx = tid; idx < 48*96; idx += 704) {
        int k2 = idx / 96, c = idx % 96;
        int row = (c < 32) ? (h*HD + c)
                : (c < 64) ? (DIM + h*HD + (c-32))
                           : (2*DIM + h*HD + (c-64));
        const float* wr = Wqkv + (size_t)row*DIM + 2*k2;
        Wp[k2*104 + c] = pack_bf16(wr[0], wr[1]);
    }
    if (tid < 96) {
        int c = tid;
        int row = (c < 32) ? (h*HD + c)
                : (c < 64) ? (DIM + h*HD + (c-32))
                           : (2*DIM + h*HD + (c-64));
        bis[c] = bqkv[row];
    }

    // ---- phase 1: two-pass bf16 MMA GEMM over k (R13 proven) ----
    float c4[12][4];
    #pragma unroll
    for (int nt = 0; nt < 12; ++nt)
        #pragma unroll
        for (int e = 0; e < 4; ++e) c4[nt][e] = 0.f;

    for (int pass = 0; pass < 2; ++pass) {
        if (pass) __syncthreads();
        for (int idx = tid; idx < 352*24; idx += 704) {
            int n = idx / 24, p = idx % 24;
            float a = 0.f, cc = 0.f;
            if (n < NTOK) {
                const float* src = (n == 0) ? (gt + (size_t)b*DIM)
                                            : (x + ((size_t)b*NQ + (n-1))*DIM);
                float2 v2 = *(const float2*)(src + pass*48 + 2*p);
                a = v2.x; cc = v2.y;
            }
            Xp[n*26 + p] = pack_bf16(a, cc);
        }
        __syncthreads();
        uint32_t xa[3][4];
        #pragma unroll
        for (int kt = 0; kt < 3; ++kt) {
            xa[kt][0] = Xp[(mb+g)*26   + kt*8 + tg];
            xa[kt][1] = Xp[(mb+g+8)*26 + kt*8 + tg];
            xa[kt][2] = Xp[(mb+g)*26   + kt*8 + tg + 4];
            xa[kt][3] = Xp[(mb+g+8)*26 + kt*8 + tg + 4];
        }
        #pragma unroll
        for (int nt = 0; nt < 12; ++nt)
            #pragma unroll
            for (int kt = 0; kt < 3; ++kt) {
                int kr = (pass*3 + kt)*8 + tg;
                uint32_t b0 = Wp[kr*104 + nt*8 + g];
                uint32_t b1 = Wp[(kr+4)*104 + nt*8 + g];
                MMA_BF16(c4[nt], xa[kt][0], xa[kt][1], xa[kt][2], xa[kt][3], b0, b1);
            }
    }
    // epilogue: f32 Q (pair-interleaved, pre-scaled) / Kt / V
    #pragma unroll
    for (int nt = 0; nt < 12; ++nt) {
        float bia = bis[nt*8 + 2*tg];
        float bib = bis[nt*8 + 2*tg + 1];
        float v0 = c4[nt][0] + bia, v1 = c4[nt][1] + bib;
        float v2 = c4[nt][2] + bia, v3 = c4[nt][3] + bib;
        const int sec = nt >> 2, ntr = nt & 3;
        const int d0 = ntr*8 + 2*tg;
        const int n1 = mb + g, n2 = n1 + 8;
        if (sec == 0) {
            Qs[(n1>>1)*68 + d0*2     + (n1&1)] = v0*scale;
            Qs[(n1>>1)*68 + (d0+1)*2 + (n1&1)] = v1*scale;
            Qs[(n2>>1)*68 + d0*2     + (n2&1)] = v2*scale;
            Qs[(n2>>1)*68 + (d0+1)*2 + (n2&1)] = v3*scale;
        } else if (sec == 1) {
            Kt[d0*356 + n1] = v0; Kt[(d0+1)*356 + n1] = v1;
            Kt[d0*356 + n2] = v2; Kt[(d0+1)*356 + n2] = v3;
        } else {
            Vs[n1*36 + d0] = v0; Vs[n1*36 + d0 + 1] = v1;
            Vs[n2*36 + d0] = v2; Vs[n2*36 + d0 + 1] = v3;
        }
    }
    __syncthreads();

    // ---- phase 2: f32x2 attention (R13 body, peeled + hoisted) ----
    const int tq = lane >> 3;
    const int tk = lane & 7;
    u64* Pw = (u64*)(smem + wid*2112);
    const float* bmb = g_bm + ((size_t)(h*NW + w)) * NQ * BMSTR;
    const int q0 = mb + tq*4;
    const int pr0 = tq*2;

    // hoisted per-row bm offsets (32-bit); <0 means invalid row
    int bmo[4];
    #pragma unroll
    for (int a = 0; a < 4; ++a) {
        int n = q0 + a;
        bmo[a] = ((n >= 1) && (n < NTOK)) ? ((n-1)*BMSTR + tk*4) : -1;
    }

    u64 o2[2][4];
    float l4[4] = {0.f, 0.f, 0.f, 0.f};
    #pragma unroll
    for (int p = 0; p < 2; ++p)
        #pragma unroll
        for (int c = 0; c < 4; ++c) o2[p][c] = pk2(0.f, 0.f);

    auto kb_body = [&](const int kbase, const bool check) {
        // bm loads for this key block (hoisted offsets)
        float4 bmv[4];
        #pragma unroll
        for (int a = 0; a < 4; ++a)
            bmv[a] = (bmo[a] >= 0) ? __ldg((const float4*)(bmb + bmo[a] + kbase))
                                   : make_float4(0.f, 0.f, 0.f, 0.f);

        // S = Q K^T
        u64 acc2[2][4];
        #pragma unroll
        for (int p = 0; p < 2; ++p)
            #pragma unroll
            for (int c = 0; c < 4; ++c) acc2[p][c] = pk2(0.f, 0.f);

        const float* kp = Kt + kbase + tk*4;
        const float* qp = Qs + (q0>>1)*68;
        #pragma unroll 8
        for (int d = 0; d < 32; ++d) {
            u64 qa = *(const u64*)(qp + 2*d);
            u64 qb = *(const u64*)(qp + 68 + 2*d);
            float4 kv = *(const float4*)(kp + d*356);
            u64 k20 = pk2(kv.x, kv.x), k21 = pk2(kv.y, kv.y);
            u64 k22 = pk2(kv.z, kv.z), k23 = pk2(kv.w, kv.w);
            fma2(acc2[0][0], qa, k20); fma2(acc2[0][1], qa, k21);
            fma2(acc2[0][2], qa, k22); fma2(acc2[0][3], qa, k23);
            fma2(acc2[1][0], qb, k20); fma2(acc2[1][1], qb, k21);
            fma2(acc2[1][2], qb, k22); fma2(acc2[1][3], qb, k23);
        }

        // exp2 (+bm); j-bound checks only on the peeled last block
        #pragma unroll
        for (int p = 0; p < 2; ++p) {
            float be[4] = {bmv[2*p].x,   bmv[2*p].y,   bmv[2*p].z,   bmv[2*p].w};
            float bo[4] = {bmv[2*p+1].x, bmv[2*p+1].y, bmv[2*p+1].z, bmv[2*p+1].w};
            #pragma unroll
            for (int c = 0; c < 4; ++c) {
                float se, so;
                upk2(se, so, acc2[p][c]);
                float pe, po;
                if (check) {
                    int j = kbase + tk*4 + c;
                    pe = (j < NTOK) ? ex2f(se + be[c]) : 0.f;
                    po = (j < NTOK) ? ex2f(so + bo[c]) : 0.f;
                } else {
                    pe = ex2f(se + be[c]);
                    po = ex2f(so + bo[c]);
                }
                l4[2*p]   += pe;
                l4[2*p+1] += po;
                Pw[(pr0 + p)*33 + tk*4 + c] = pk2(pe, po);
            }
        }
        __syncwarp();

        // O += P V
        const float* vp = Vs + (size_t)kbase*36 + tk*4;
        #pragma unroll 8
        for (int j = 0; j < 32; ++j) {
            u64 p20 = Pw[pr0*33 + j];
            u64 p21 = Pw[(pr0+1)*33 + j];
            float4 vv = *(const float4*)(vp + j*36);
            u64 v20 = pk2(vv.x, vv.x), v21 = pk2(vv.y, vv.y);
            u64 v22 = pk2(vv.z, vv.z), v23 = pk2(vv.w, vv.w);
            fma2(o2[0][0], p20, v20); fma2(o2[0][1], p20, v21);
            fma2(o2[0][2], p20, v22); fma2(o2[0][3], p20, v23);
            fma2(o2[1][0], p21, v20); fma2(o2[1][1], p21, v21);
            fma2(o2[1][2], p21, v22); fma2(o2[1][3], p21, v23);
        }
        __syncwarp();
    };

    #pragma unroll 1
    for (int kb = 0; kb < 10; ++kb)
        kb_body(kb*32, false);
    kb_body(320, true);

    #pragma unroll
    for (int a = 0; a < 4; ++a) {
        l4[a] += __shfl_xor_sync(0xffffffffu, l4[a], 1);
        l4[a] += __shfl_xor_sync(0xffffffffu, l4[a], 2);
        l4[a] += __shfl_xor_sync(0xffffffffu, l4[a], 4);
    }
    #pragma unroll
    for (int p = 0; p < 2; ++p) {
        float oe[4], oo[4];
        #pragma unroll
        for (int c = 0; c < 4; ++c) upk2(oe[c], oo[c], o2[p][c]);
        int re = q0 + 2*p, ro = re + 1;
        if (re < NTOK) {
            float inv = 1.f / l4[2*p];
            *(float4*)(g_att + ((size_t)b*NTOK + re)*DIM + h*HD + tk*4) =
                make_float4(oe[0]*inv, oe[1]*inv, oe[2]*inv, oe[3]*inv);
        }
        if (ro < NTOK) {
            float inv = 1.f / l4[2*p+1];
            *(float4*)(g_att + ((size_t)b*NTOK + ro)*DIM + h*HD + tk*4) =
                make_float4(oo[0]*inv, oo[1]*inv, oo[2]*inv, oo[3]*inv);
        }
    }
}

// ---------------- proj: R12 proven f32x2 version (unchanged) ----------------
#define PROJ_SMEM (25088 + 38784)
__global__ void __launch_bounds__(256, 3)
proj_kernel(const float* __restrict__ W,
            const float* __restrict__ bp,
            float* __restrict__ dout) {
    extern __shared__ char psm[];
    float* Ai  = (float*)psm;               // [32][196]
    float* Wsm = (float*)(psm + 25088);     // [96][101]
    const int tid  = threadIdx.x;
    const int row0 = blockIdx.x * 64;
    const int rg = tid >> 5;
    const int cg = tid & 31;

    for (int idx = tid; idx < 32*24; idx += 256) {
        int rp = idx / 24, kq = idx % 24;
        float4 e = *(const float4*)(g_att + (size_t)(row0 + 2*rp)*DIM + 4*kq);
        float4 o = *(const float4*)(g_att + (size_t)(row0 + 2*rp + 1)*DIM + 4*kq);
        *(float4*)&Ai[rp*196 + 8*kq]     = make_float4(e.x, o.x, e.y, o.y);
        *(float4*)&Ai[rp*196 + 8*kq + 4] = make_float4(e.z, o.z, e.w, o.w);
    }
    for (int idx = tid; idx < 96*24; idx += 256) {
        int c = idx / 24, kq = idx % 24;
        float4 wv = *(const float4*)(W + (size_t)c*DIM + 4*kq);
        Wsm[c*101 + 4*kq]     = wv.x;
        Wsm[c*101 + 4*kq + 1] = wv.y;
        Wsm[c*101 + 4*kq + 2] = wv.z;
        Wsm[c*101 + 4*kq + 3] = wv.w;
    }
    __syncthreads();

    u64 a2[4][3];
    #pragma unroll
    for (int i = 0; i < 4; ++i)
        #pragma unroll
        for (int j = 0; j < 3; ++j) a2[i][j] = pk2(0.f, 0.f);

    const float* arow = Ai + rg*4*196;
    const float* wrow = Wsm + cg*3*101;
    #pragma unroll 4
    for (int k = 0; k < 96; ++k) {
        u64 x2[4];
        #pragma unroll
        for (int i = 0; i < 4; ++i)
            x2[i] = *(const u64*)(arow + i*196 + 2*k);
        u64 w0 = pk2(wrow[k],       wrow[k]);
        u64 w1 = pk2(wrow[101 + k], wrow[101 + k]);
        u64 w2 = pk2(wrow[202 + k], wrow[202 + k]);
        #pragma unroll
        for (int i = 0; i < 4; ++i) {
            fma2(a2[i][0], x2[i], w0);
            fma2(a2[i][1], x2[i], w1);
            fma2(a2[i][2], x2[i], w2);
        }
    }

    #pragma unroll
    for (int i = 0; i < 4; ++i) {
        #pragma unroll
        for (int j = 0; j < 3; ++j) {
            float ve, vo;
            upk2(ve, vo, a2[i][j]);
            int c = cg*3 + j;
            float bb = __ldg(bp + c);
            ve += bb; vo += bb;
            int gre = row0 + (rg*4 + i)*2;
            int gro = gre + 1;
            int be_ = gre / NTOK, ne = gre % NTOK;
            int bo_ = gro / NTOK, no = gro % NTOK;
            if (ne == 0) dout[XOUT_SZ + (size_t)be_*DIM + c] = ve;
            else         dout[((size_t)be_*NQ + (ne-1))*DIM + c] = ve;
            if (no == 0) dout[XOUT_SZ + (size_t)bo_*DIM + c] = vo;
            else         dout[((size_t)bo_*NQ + (no-1))*DIM + c] = vo;
        }
    }
}

// ---------------- launch ----------------
extern "C" void kernel_launch(void* const* d_in, const int* in_sizes, int n_in,
                              void* d_out, int out_size) {
    const float* x     = (const float*)d_in[0];
    const float* gt    = (const float*)d_in[1];
    const float* mask  = (const float*)d_in[2];
    const int*   ri    = (const int*)  d_in[3];
    const float* Wqkv  = (const float*)d_in[4];
    const float* bqkv  = (const float*)d_in[5];
    const float* Wproj = (const float*)d_in[6];
    const float* bproj = (const float*)d_in[7];
    const float* btab  = (const float*)d_in[8];
    float* out = (float*)d_out;

    cudaFuncSetAttribute(fused_attn_kernel, cudaFuncAttributeMaxDynamicSharedMemorySize, FUSED_SMEM);
    cudaFuncSetAttribute(proj_kernel,       cudaFuncAttributeMaxDynamicSharedMemorySize, PROJ_SMEM);

    {
        size_t total = (size_t)H*NW*NQ*86;
        bm_pre_kernel<<<(unsigned)((total + 255)/256), 256>>>(btab, ri, mask);
    }
    fused_attn_kernel<<<B_*H, 704, FUSED_SMEM>>>(x, gt, Wqkv, bqkv);
    proj_kernel<<<NROWS/64, 256, PROJ_SMEM>>>(Wproj, bproj, out);
}

// round 17
// speedup vs baseline: 1.6184x; 1.0192x over previous
#include <cuda_runtime.h>
#include <cuda_bf16.h>
#include <math.h>
#include <stdint.h>

#define B_   512
#define NW   64
#define NQ   343
#define NTOK 344
#define DIM  96
#define H    3
#define HD   32
#define NROWS (B_*NTOK)
#define XOUT_SZ ((size_t)B_*NQ*DIM)
#define BMSTR 344
#define RLN2  1.4426950408889634f

typedef unsigned long long u64;

__device__ float g_att[(size_t)B_*NTOK*DIM];
__device__ float g_bm[(size_t)H*NW*NQ*BMSTR + 16];

// ---------------- kernel 0: bm gather, 3 heads per thread ----------------
__global__ void bm_pre_kernel(const float* __restrict__ btab,
                              const int* __restrict__ ri,
                              const float* __restrict__ mask) {
    size_t gid = (size_t)blockIdx.x * 256 + threadIdx.x;
    if (gid >= (size_t)NW*NQ*86) return;
    int q  = (int)(gid % 86);
    size_t t = gid / 86;
    int r  = (int)(t % NQ);
    int w  = (int)(t / NQ);
    int j0 = q*4;
    const int*   rr = ri + (size_t)r*NQ;
    const float* mr = mask + (size_t)w*NQ*NQ + (size_t)r*NQ;
    float v0[4], v1[4], v2[4];
    #pragma unroll
    for (int e = 0; e < 4; ++e) {
        int j = j0 + e;
        v0[e] = 0.f; v1[e] = 0.f; v2[e] = 0.f;
        if (j >= 1) {
            int rv = rr[j-1];
            float m = mr[j-1];
            v0[e] = (btab[rv*H + 0] + m) * RLN2;
            v1[e] = (btab[rv*H + 1] + m) * RLN2;
            v2[e] = (btab[rv*H + 2] + m) * RLN2;
        }
    }
    size_t base = ((size_t)w*NQ + r)*BMSTR + j0;
    size_t hstride = (size_t)NW*NQ*BMSTR;
    *(float4*)&g_bm[base]             = make_float4(v0[0], v0[1], v0[2], v0[3]);
    *(float4*)&g_bm[base + hstride]   = make_float4(v1[0], v1[1], v1[2], v1[3]);
    *(float4*)&g_bm[base + 2*hstride] = make_float4(v2[0], v2[1], v2[2], v2[3]);
}

// ---------------- helpers ----------------
__device__ __forceinline__ uint32_t pack_bf16(float lo, float hi) {
    uint32_t r;
    asm("cvt.rn.bf16x2.f32 %0, %1, %2;" : "=r"(r) : "f"(hi), "f"(lo));
    return r;
}
__device__ __forceinline__ u64 pk2(float lo, float hi) {
    u64 r; asm("mov.b64 %0, {%1, %2};" : "=l"(r) : "f"(lo), "f"(hi)); return r;
}
__device__ __forceinline__ void upk2(float& lo, float& hi, u64 v) {
    asm("mov.b64 {%0, %1}, %2;" : "=f"(lo), "=f"(hi) : "l"(v));
}
__device__ __forceinline__ void fma2(u64& d, u64 a, u64 b) {
    asm("fma.rn.f32x2 %0, %1, %2, %3;" : "=l"(d) : "l"(a), "l"(b), "l"(d));
}
__device__ __forceinline__ float ex2f(float x) {
    float r; asm("ex2.approx.f32 %0, %1;" : "=f"(r) : "f"(x)); return r;
}

#define MMA_BF16(d, a0,a1,a2,a3, b0,b1)                                      \
    asm volatile("mma.sync.aligned.m16n8k16.row.col.f32.bf16.bf16.f32 "      \
        "{%0,%1,%2,%3},{%4,%5,%6,%7},{%8,%9},{%0,%1,%2,%3};"                 \
        : "+f"(d[0]), "+f"(d[1]), "+f"(d[2]), "+f"(d[3])                      \
        : "r"(a0), "r"(a1), "r"(a2), "r"(a3), "r"(b0), "r"(b1))

// fused smem layout (bytes):
//  phase1 aliases: Xp u32[352][26] @0 | Wp u32[48][104] @36608 | bis @56576
//  phase2: P u64/warp [8][34] @wid*2176, region [0,47872)
//          Qs @56960 | Kt @104832 | Vs @150400
#define SM_XP   0
#define SM_WP   36608
#define SM_BS   56576
#define SM_QS   56960
#define SM_KT   104832
#define SM_VS   150400
#define FUSED_SMEM 201088

__global__ void __launch_bounds__(704, 1)
fused_attn_kernel(const float* __restrict__ x,
                  const float* __restrict__ gt,
                  const float* __restrict__ Wqkv,
                  const float* __restrict__ bqkv) {
    extern __shared__ char smem[];
    uint32_t* Xp = (uint32_t*)(smem + SM_XP);
    uint32_t* Wp = (uint32_t*)(smem + SM_WP);
    float* bis = (float*)(smem + SM_BS);
    float* Qs  = (float*)(smem + SM_QS);
    float* Kt  = (float*)(smem + SM_KT);
    float* Vs  = (float*)(smem + SM_VS);

    const int bid = blockIdx.x;
    const int rep = bid & 7;
    const int hw  = bid >> 3;
    const int w   = hw & 63;
    const int h   = hw >> 6;
    const int b   = (rep << 6) + w;

    const int tid  = threadIdx.x;
    const int wid  = tid >> 5;
    const int lane = tid & 31;
    const int g    = lane >> 2;
    const int tg   = lane & 3;
    const float scale = 0.17677669529663687f * RLN2;
    const int mb = wid * 16;

    // ---- W and bias fill (once) ----
    for (int idx = tid; idx < 48*96; idx += 704) {
        int k2 = idx / 96, c = idx % 96;
        int row = (c < 32) ? (h*HD + c)
                : (c < 64) ? (DIM + h*HD + (c-32))
                           : (2*DIM + h*HD + (c-64));
        const float* wr = Wqkv + (size_t)row*DIM + 2*k2;
        Wp[k2*104 + c] = pack_bf16(wr[0], wr[1]);
    }
    if (tid < 96) {
        int c = tid;
        int row = (c < 32) ? (h*HD + c)
                : (c < 64) ? (DIM + h*HD + (c-32))
                           : (2*DIM + h*HD + (c-64));
        bis[c] = bqkv[row];
    }

    // ---- phase 1: two-pass bf16 MMA GEMM over k (R13 proven) ----
    float c4[12][4];
    #pragma unroll
    for (int nt = 0; nt < 12; ++nt)
        #pragma unroll
        for (int e = 0; e < 4; ++e) c4[nt][e] = 0.f;

    for (int pass = 0; pass < 2; ++pass) {
        if (pass) __syncthreads();
        for (int idx = tid; idx < 352*24; idx += 704) {
            int n = idx / 24, p = idx % 24;
            float a = 0.f, cc = 0.f;
            if (n < NTOK) {
                const float* src = (n == 0) ? (gt + (size_t)b*DIM)
                                            : (x + ((size_t)b*NQ + (n-1))*DIM);
                float2 v2 = *(const float2*)(src + pass*48 + 2*p);
                a = v2.x; cc = v2.y;
            }
            Xp[n*26 + p] = pack_bf16(a, cc);
        }
        __syncthreads();
        uint32_t xa[3][4];
        #pragma unroll
        for (int kt = 0; kt < 3; ++kt) {
            xa[kt][0] = Xp[(mb+g)*26   + kt*8 + tg];
            xa[kt][1] = Xp[(mb+g+8)*26 + kt*8 + tg];
            xa[kt][2] = Xp[(mb+g)*26   + kt*8 + tg + 4];
            xa[kt][3] = Xp[(mb+g+8)*26 + kt*8 + tg + 4];
        }
        #pragma unroll
        for (int nt = 0; nt < 12; ++nt)
            #pragma unroll
            for (int kt = 0; kt < 3; ++kt) {
                int kr = (pass*3 + kt)*8 + tg;
                uint32_t b0 = Wp[kr*104 + nt*8 + g];
                uint32_t b1 = Wp[(kr+4)*104 + nt*8 + g];
                MMA_BF16(c4[nt], xa[kt][0], xa[kt][1], xa[kt][2], xa[kt][3], b0, b1);
            }
    }
    // epilogue: f32 Q (pair-interleaved, pre-scaled) / Kt / V
    #pragma unroll
    for (int nt = 0; nt < 12; ++nt) {
        float bia = bis[nt*8 + 2*tg];
        float bib = bis[nt*8 + 2*tg + 1];
        float v0 = c4[nt][0] + bia, v1 = c4[nt][1] + bib;
        float v2 = c4[nt][2] + bia, v3 = c4[nt][3] + bib;
        const int sec = nt >> 2, ntr = nt & 3;
        const int d0 = ntr*8 + 2*tg;
        const int n1 = mb + g, n2 = n1 + 8;
        if (sec == 0) {
            Qs[(n1>>1)*68 + d0*2     + (n1&1)] = v0*scale;
            Qs[(n1>>1)*68 + (d0+1)*2 + (n1&1)] = v1*scale;
            Qs[(n2>>1)*68 + d0*2     + (n2&1)] = v2*scale;
            Qs[(n2>>1)*68 + (d0+1)*2 + (n2&1)] = v3*scale;
        } else if (sec == 1) {
            Kt[d0*356 + n1] = v0; Kt[(d0+1)*356 + n1] = v1;
            Kt[d0*356 + n2] = v2; Kt[(d0+1)*356 + n2] = v3;
        } else {
            Vs[n1*36 + d0] = v0; Vs[n1*36 + d0 + 1] = v1;
            Vs[n2*36 + d0] = v2; Vs[n2*36 + d0 + 1] = v3;
        }
    }
    __syncthreads();

    // ---- phase 2: f32x2 attention, paired loads ----
    const int tq = lane >> 3;
    const int tk = lane & 7;
    u64* Pw = (u64*)(smem + wid*2176);   // [8 pair-rows][34]
    const float* bmb = g_bm + ((size_t)(h*NW + w)) * NQ * BMSTR;
    const int q0 = mb + tq*4;
    const int pr0 = tq*2;

    u64 o2[2][4];
    float l4[4] = {0.f, 0.f, 0.f, 0.f};
    #pragma unroll
    for (int p = 0; p < 2; ++p)
        #pragma unroll
        for (int c = 0; c < 4; ++c) o2[p][c] = pk2(0.f, 0.f);

    #pragma unroll 1
    for (int kb = 0; kb < 11; ++kb) {
        const int kbase = kb*32;

        // ---- S = Q K^T (2d per step, paired loads) ----
        u64 acc2[2][4];
        #pragma unroll
        for (int p = 0; p < 2; ++p)
            #pragma unroll
            for (int c = 0; c < 4; ++c) acc2[p][c] = pk2(0.f, 0.f);

        const float* kp = Kt + kbase + tk*4;
        const float* qp = Qs + (q0>>1)*68;
        #pragma unroll 4
        for (int d = 0; d < 32; d += 2) {
            ulonglong2 qa2 = *(const ulonglong2*)(qp + 2*d);
            ulonglong2 qb2 = *(const ulonglong2*)(qp + 68 + 2*d);
            float4 kv0 = *(const float4*)(kp + d*356);
            {
                u64 s0 = pk2(kv0.x, kv0.x), s1 = pk2(kv0.y, kv0.y);
                u64 s2 = pk2(kv0.z, kv0.z), s3 = pk2(kv0.w, kv0.w);
                fma2(acc2[0][0], qa2.x, s0); fma2(acc2[0][1], qa2.x, s1);
                fma2(acc2[0][2], qa2.x, s2); fma2(acc2[0][3], qa2.x, s3);
                fma2(acc2[1][0], qb2.x, s0); fma2(acc2[1][1], qb2.x, s1);
                fma2(acc2[1][2], qb2.x, s2); fma2(acc2[1][3], qb2.x, s3);
            }
            float4 kv1 = *(const float4*)(kp + (d+1)*356);
            {
                u64 s0 = pk2(kv1.x, kv1.x), s1 = pk2(kv1.y, kv1.y);
                u64 s2 = pk2(kv1.z, kv1.z), s3 = pk2(kv1.w, kv1.w);
                fma2(acc2[0][0], qa2.y, s0); fma2(acc2[0][1], qa2.y, s1);
                fma2(acc2[0][2], qa2.y, s2); fma2(acc2[0][3], qa2.y, s3);
                fma2(acc2[1][0], qb2.y, s0); fma2(acc2[1][1], qb2.y, s1);
                fma2(acc2[1][2], qb2.y, s2); fma2(acc2[1][3], qb2.y, s3);
            }
        }

        // ---- exp2 + bm; P stores paired (STS.128) ----
        #pragma unroll
        for (int p = 0; p < 2; ++p) {
            int re = q0 + 2*p, ro = re + 1;
            bool vqe = (re >= 1) && (re < NTOK);
            bool vqo = (ro < NTOK);
            float4 bme = vqe ? __ldg((const float4*)(bmb + (size_t)(re-1)*BMSTR + kbase + tk*4))
                             : make_float4(0.f,0.f,0.f,0.f);
            float4 bmo = vqo ? __ldg((const float4*)(bmb + (size_t)(ro-1)*BMSTR + kbase + tk*4))
                             : make_float4(0.f,0.f,0.f,0.f);
            float be[4] = {bme.x, bme.y, bme.z, bme.w};
            float bo[4] = {bmo.x, bmo.y, bmo.z, bmo.w};
            u64 pp[4];
            #pragma unroll
            for (int c = 0; c < 4; ++c) {
                float se, so;
                upk2(se, so, acc2[p][c]);
                int j = kbase + tk*4 + c;
                float pe = (j < NTOK) ? ex2f(se + be[c]) : 0.f;
                float po = (j < NTOK) ? ex2f(so + bo[c]) : 0.f;
                l4[2*p]   += pe;
                l4[2*p+1] += po;
                pp[c] = pk2(pe, po);
            }
            ulonglong2 st0; st0.x = pp[0]; st0.y = pp[1];
            ulonglong2 st1; st1.x = pp[2]; st1.y = pp[3];
            *(ulonglong2*)&Pw[(pr0 + p)*34 + tk*4]     = st0;
            *(ulonglong2*)&Pw[(pr0 + p)*34 + tk*4 + 2] = st1;
        }
        __syncwarp();

        // ---- O += P V (2j per step, paired P loads) ----
        const float* vp = Vs + (size_t)kbase*36 + tk*4;
        #pragma unroll 4
        for (int j = 0; j < 32; j += 2) {
            ulonglong2 pA = *(const ulonglong2*)&Pw[pr0*34 + j];
            ulonglong2 pB = *(const ulonglong2*)&Pw[(pr0+1)*34 + j];
            float4 vv0 = *(const float4*)(vp + j*36);
            {
                u64 s0 = pk2(vv0.x, vv0.x), s1 = pk2(vv0.y, vv0.y);
                u64 s2 = pk2(vv0.z, vv0.z), s3 = pk2(vv0.w, vv0.w);
                fma2(o2[0][0], pA.x, s0); fma2(o2[0][1], pA.x, s1);
                fma2(o2[0][2], pA.x, s2); fma2(o2[0][3], pA.x, s3);
                fma2(o2[1][0], pB.x, s0); fma2(o2[1][1], pB.x, s1);
                fma2(o2[1][2], pB.x, s2); fma2(o2[1][3], pB.x, s3);
            }
            float4 vv1 = *(const float4*)(vp + (j+1)*36);
            {
                u64 s0 = pk2(vv1.x, vv1.x), s1 = pk2(vv1.y, vv1.y);
                u64 s2 = pk2(vv1.z, vv1.z), s3 = pk2(vv1.w, vv1.w);
                fma2(o2[0][0], pA.y, s0); fma2(o2[0][1], pA.y, s1);
                fma2(o2[0][2], pA.y, s2); fma2(o2[0][3], pA.y, s3);
                fma2(o2[1][0], pB.y, s0); fma2(o2[1][1], pB.y, s1);
                fma2(o2[1][2], pB.y, s2); fma2(o2[1][3], pB.y, s3);
            }
        }
        __syncwarp();
    }

    #pragma unroll
    for (int a = 0; a < 4; ++a) {
        l4[a] += __shfl_xor_sync(0xffffffffu, l4[a], 1);
        l4[a] += __shfl_xor_sync(0xffffffffu, l4[a], 2);
        l4[a] += __shfl_xor_sync(0xffffffffu, l4[a], 4);
    }
    #pragma unroll
    for (int p = 0; p < 2; ++p) {
        float oe[4], oo[4];
        #pragma unroll
        for (int c = 0; c < 4; ++c) upk2(oe[c], oo[c], o2[p][c]);
        int re = q0 + 2*p, ro = re + 1;
        if (re < NTOK) {
            float inv = 1.f / l4[2*p];
            *(float4*)(g_att + ((size_t)b*NTOK + re)*DIM + h*HD + tk*4) =
                make_float4(oe[0]*inv, oe[1]*inv, oe[2]*inv, oe[3]*inv);
        }
        if (ro < NTOK) {
            float inv = 1.f / l4[2*p+1];
            *(float4*)(g_att + ((size_t)b*NTOK + ro)*DIM + h*HD + tk*4) =
                make_float4(oo[0]*inv, oo[1]*inv, oo[2]*inv, oo[3]*inv);
        }
    }
}

// ---------------- proj: R12 proven f32x2 version (unchanged) ----------------
#define PROJ_SMEM (25088 + 38784)
__global__ void __launch_bounds__(256, 3)
proj_kernel(const float* __restrict__ W,
            const float* __restrict__ bp,
            float* __restrict__ dout) {
    extern __shared__ char psm[];
    float* Ai  = (float*)psm;               // [32][196]
    float* Wsm = (float*)(psm + 25088);     // [96][101]
    const int tid  = threadIdx.x;
    const int row0 = blockIdx.x * 64;
    const int rg = tid >> 5;
    const int cg = tid & 31;

    for (int idx = tid; idx < 32*24; idx += 256) {
        int rp = idx / 24, kq = idx % 24;
        float4 e = *(const float4*)(g_att + (size_t)(row0 + 2*rp)*DIM + 4*kq);
        float4 o = *(const float4*)(g_att + (size_t)(row0 + 2*rp + 1)*DIM + 4*kq);
        *(float4*)&Ai[rp*196 + 8*kq]     = make_float4(e.x, o.x, e.y, o.y);
        *(float4*)&Ai[rp*196 + 8*kq + 4] = make_float4(e.z, o.z, e.w, o.w);
    }
    for (int idx = tid; idx < 96*24; idx += 256) {
        int c = idx / 24, kq = idx % 24;
        float4 wv = *(const float4*)(W + (size_t)c*DIM + 4*kq);
        Wsm[c*101 + 4*kq]     = wv.x;
        Wsm[c*101 + 4*kq + 1] = wv.y;
        Wsm[c*101 + 4*kq + 2] = wv.z;
        Wsm[c*101 + 4*kq + 3] = wv.w;
    }
    __syncthreads();

    u64 a2[4][3];
    #pragma unroll
    for (int i = 0; i < 4; ++i)
        #pragma unroll
        for (int j = 0; j < 3; ++j) a2[i][j] = pk2(0.f, 0.f);

    const float* arow = Ai + rg*4*196;
    const float* wrow = Wsm + cg*3*101;
    #pragma unroll 4
    for (int k = 0; k < 96; ++k) {
        u64 x2[4];
        #pragma unroll
        for (int i = 0; i < 4; ++i)
            x2[i] = *(const u64*)(arow + i*196 + 2*k);
        u64 w0 = pk2(wrow[k],       wrow[k]);
        u64 w1 = pk2(wrow[101 + k], wrow[101 + k]);
        u64 w2 = pk2(wrow[202 + k], wrow[202 + k]);
        #pragma unroll
        for (int i = 0; i < 4; ++i) {
            fma2(a2[i][0], x2[i], w0);
            fma2(a2[i][1], x2[i], w1);
            fma2(a2[i][2], x2[i], w2);
        }
    }

    #pragma unroll
    for (int i = 0; i < 4; ++i) {
        #pragma unroll
        for (int j = 0; j < 3; ++j) {
            float ve, vo;
            upk2(ve, vo, a2[i][j]);
            int c = cg*3 + j;
            float bb = __ldg(bp + c);
            ve += bb; vo += bb;
            int gre = row0 + (rg*4 + i)*2;
            int gro = gre + 1;
            int be_ = gre / NTOK, ne = gre % NTOK;
            int bo_ = gro / NTOK, no = gro % NTOK;
            if (ne == 0) dout[XOUT_SZ + (size_t)be_*DIM + c] = ve;
            else         dout[((size_t)be_*NQ + (ne-1))*DIM + c] = ve;
            if (no == 0) dout[XOUT_SZ + (size_t)bo_*DIM + c] = vo;
            else         dout[((size_t)bo_*NQ + (no-1))*DIM + c] = vo;
        }
    }
}

// ---------------- launch ----------------
extern "C" void kernel_launch(void* const* d_in, const int* in_sizes, int n_in,
                              void* d_out, int out_size) {
    const float* x     = (const float*)d_in[0];
    const float* gt    = (const float*)d_in[1];
    const float* mask  = (const float*)d_in[2];
    const int*   ri    = (const int*)  d_in[3];
    const float* Wqkv  = (const float*)d_in[4];
    const float* bqkv  = (const float*)d_in[5];
    const float* Wproj = (const float*)d_in[6];
    const float* bproj = (const float*)d_in[7];
    const float* btab  = (const float*)d_in[8];
    float* out = (float*)d_out;

    cudaFuncSetAttribute(fused_attn_kernel, cudaFuncAttributeMaxDynamicSharedMemorySize, FUSED_SMEM);
    cudaFuncSetAttribute(proj_kernel,       cudaFuncAttributeMaxDynamicSharedMemorySize, PROJ_SMEM);

    {
        size_t total = (size_t)NW*NQ*86;
        bm_pre_kernel<<<(unsigned)((total + 255)/256), 256>>>(btab, ri, mask);
    }
    fused_attn_kernel<<<B_*H, 704, FUSED_SMEM>>>(x, gt, Wqkv, bqkv);
    proj_kernel<<<NROWS/64, 256, PROJ_SMEM>>>(Wproj, bproj, out);
}